// round 10
// baseline (speedup 1.0000x reference)
#include <cuda_runtime.h>
#include <cuda_bf16.h>
#include <math.h>
#include <stdint.h>

// ---------------- problem constants ----------------
#define HH 50
#define WW 50
#define NPOS 2500          // H*W
#define DIM 256
#define HEADS 8
#define DH 64
#define G 4
#define INNER 512          // HEADS*DH
#define OFFD 128           // INNER/G
#define KS 6
#define DF 4
#define PAD 1
#define HK 12
#define JJ 144             // HK*HK
#define SCALE 0.125f
#define OFF_SCALE 4.0f
#define SEQ 2501           // H*W+1

// fused_attn smem layout (bytes, all 16-aligned)
#define PS_F    (2 * 32 * 148)              // score/bias tile, floats
#define PS_B    (PS_F * 4)                  // 37888
#define H1_B    (128 * 40 * 4)              // 20480
#define QS_B    (32 * 65 * 4)               // 8320
#define W2S_B   (32 * 72 * 4)               // 9216
#define VGS_B   (288 * 4)                   // 1152
#define WX_B    (32 * 4)                    // 128 (x3)
#define B2S_B   256
#define W3S_B   512
#define RS_B    128
#define FA_SMEM (PS_B + H1_B + QS_B + W2S_B + VGS_B + 3 * WX_B + B2S_B + W3S_B + RS_B)

// ---------------- scratch (device globals, no allocation) ----------------
__device__ float g_q[INNER * NPOS];
__device__ float g_off1[INNER * JJ];
__device__ float g_vgs[G * JJ * 2];
__device__ float g_kv[DIM * JJ];
__device__ float g_k[INNER * JJ];
__device__ float g_v[INNER * JJ];
__device__ float g_ao[INNER * NPOS];

// ---------------- helpers ----------------
__device__ __forceinline__ void mma_tf32(float* d, const uint32_t* a,
                                         uint32_t b0, uint32_t b1) {
    asm volatile(
        "mma.sync.aligned.m16n8k8.row.col.f32.tf32.tf32.f32 "
        "{%0,%1,%2,%3}, {%4,%5,%6,%7}, {%8,%9}, {%0,%1,%2,%3};\n"
        : "+f"(d[0]), "+f"(d[1]), "+f"(d[2]), "+f"(d[3])
        : "r"(a[0]), "r"(a[1]), "r"(a[2]), "r"(a[3]), "r"(b0), "r"(b1));
}

__device__ __forceinline__ void mma_bf16(float* d, const uint32_t* a,
                                         uint32_t b0, uint32_t b1) {
    asm volatile(
        "mma.sync.aligned.m16n8k16.row.col.f32.bf16.bf16.f32 "
        "{%0,%1,%2,%3}, {%4,%5,%6,%7}, {%8,%9}, {%0,%1,%2,%3};\n"
        : "+f"(d[0]), "+f"(d[1]), "+f"(d[2]), "+f"(d[3])
        : "r"(a[0]), "r"(a[1]), "r"(a[2]), "r"(a[3]), "r"(b0), "r"(b1));
}

__device__ __forceinline__ uint32_t f2tf32(float f) {
    uint32_t v;
    asm("cvt.rna.tf32.f32 %0, %1;" : "=r"(v) : "f"(f));
    return v;
}

__device__ __forceinline__ uint32_t pack_bf16x2(float lo, float hi) {
    __nv_bfloat162 p = __floats2bfloat162_rn(lo, hi);
    return *reinterpret_cast<uint32_t*>(&p);
}

__device__ __forceinline__ uint32_t h1_bf16x2(__nv_bfloat162 fx2, __nv_bfloat162 fy2,
                                              uint32_t wx, uint32_t wy, uint32_t bb) {
    __nv_bfloat162 r = __hfma2(fy2, *reinterpret_cast<__nv_bfloat162*>(&wy),
                               *reinterpret_cast<__nv_bfloat162*>(&bb));
    r = __hfma2(fx2, *reinterpret_cast<__nv_bfloat162*>(&wx), r);
    __nv_bfloat162 z = __floats2bfloat162_rn(0.f, 0.f);
    r = __hmax2(r, z);
    return *reinterpret_cast<uint32_t*>(&r);
}

__device__ __forceinline__ float fast_exp(float x) {
    x = fmaxf(x, -80.f);
    float t = x * 1.4426950408889634f;
    float fl = rintf(t);
    float f = t - fl;
    float p = 1.33335581e-3f;
    p = fmaf(p, f, 9.61812911e-3f);
    p = fmaf(p, f, 5.55041087e-2f);
    p = fmaf(p, f, 2.40226507e-1f);
    p = fmaf(p, f, 6.93147180e-1f);
    p = fmaf(p, f, 1.0f);
    int e = (int)fl;
    return p * __int_as_float((e + 127) << 23);
}

// ---------------- 3xTF32 split-precision tensor-core GEMM ----------------
__global__ __launch_bounds__(256)
void tf32gemm(const float* __restrict__ A, const float* __restrict__ B,
              float* __restrict__ C, int M, int N, int K,
              int ldb, int boff, int ldc, int coff,
              const float* __restrict__ bias,
              const float* __restrict__ A2, float* __restrict__ C2) {
    __shared__ uint32_t Ah[64][36], Al[64][36];
    __shared__ uint32_t Bh[32][72], Bl[32][72];
    const float* Ause = A;
    float* Cuse = C;
    if (blockIdx.z) { Ause = A2; Cuse = C2; }
    const int tid = threadIdx.x;
    const int m0 = blockIdx.y * 64, n0 = blockIdx.x * 64;
    const int wid = tid >> 5, lane = tid & 31;
    const int gid = lane >> 2, tig = lane & 3;
    const int wm = (wid >> 1) * 16, wn = (wid & 1) * 32;

    float acc[4][4];
#pragma unroll
    for (int nt = 0; nt < 4; nt++)
#pragma unroll
        for (int c = 0; c < 4; c++) acc[nt][c] = 0.f;

    for (int k0 = 0; k0 < K; k0 += 32) {
        for (int idx = tid; idx < 2048; idx += 256) {
            int m = idx >> 5, k = idx & 31;
            float v = Ause[(size_t)(m0 + m) * K + k0 + k];
            uint32_t hi = f2tf32(v);
            Ah[m][k] = hi;
            Al[m][k] = f2tf32(v - __uint_as_float(hi));
        }
        for (int idx = tid; idx < 2048; idx += 256) {
            int k = idx >> 6, n = idx & 63;
            float v = (n0 + n < N) ? B[(size_t)(k0 + k) * ldb + boff + n0 + n] : 0.f;
            uint32_t hi = f2tf32(v);
            Bh[k][n] = hi;
            Bl[k][n] = f2tf32(v - __uint_as_float(hi));
        }
        __syncthreads();
#pragma unroll
        for (int ks = 0; ks < 32; ks += 8) {
            uint32_t ah[4], al[4];
            ah[0] = Ah[wm + gid][ks + tig];
            ah[1] = Ah[wm + gid + 8][ks + tig];
            ah[2] = Ah[wm + gid][ks + tig + 4];
            ah[3] = Ah[wm + gid + 8][ks + tig + 4];
            al[0] = Al[wm + gid][ks + tig];
            al[1] = Al[wm + gid + 8][ks + tig];
            al[2] = Al[wm + gid][ks + tig + 4];
            al[3] = Al[wm + gid + 8][ks + tig + 4];
#pragma unroll
            for (int nt = 0; nt < 4; nt++) {
                int nn = wn + nt * 8 + gid;
                uint32_t bh0 = Bh[ks + tig][nn], bh1 = Bh[ks + tig + 4][nn];
                uint32_t bl0 = Bl[ks + tig][nn], bl1 = Bl[ks + tig + 4][nn];
                mma_tf32(acc[nt], ah, bh0, bh1);
                mma_tf32(acc[nt], ah, bl0, bl1);
                mma_tf32(acc[nt], al, bh0, bh1);
            }
        }
        __syncthreads();
    }

    const int row0 = m0 + wm + gid;
    const float bb0 = bias ? bias[row0] : 0.f;
    const float bb1 = bias ? bias[row0 + 8] : 0.f;
#pragma unroll
    for (int nt = 0; nt < 4; nt++) {
        int col = n0 + wn + nt * 8 + 2 * tig;
        if (col < N) {
            Cuse[(size_t)row0 * ldc + coff + col] = acc[nt][0] + bb0;
            Cuse[(size_t)(row0 + 8) * ldc + coff + col] = acc[nt][2] + bb1;
        }
        if (col + 1 < N) {
            Cuse[(size_t)row0 * ldc + coff + col + 1] = acc[nt][1] + bb0;
            Cuse[(size_t)(row0 + 8) * ldc + coff + col + 1] = acc[nt][3] + bb1;
        }
    }
}

// ---------------- depthwise conv + bias + GELU (smem-staged input) ----------------
__global__ void dconv_kernel(const float* __restrict__ w1, const float* __restrict__ b1,
                             const float* __restrict__ x1, float* __restrict__ out) {
    __shared__ float qsm[NPOS];
    const int gc = blockIdx.x;
    const int c = gc & 127;
    const int j = threadIdx.x;
    const float* qrow = &g_q[(size_t)gc * NPOS];
    for (int idx = j; idx < NPOS; idx += JJ) qsm[idx] = qrow[idx];
    if (gc == 0) {
        for (int o = j; o < DIM; o += JJ)
            out[(size_t)o * SEQ] = x1[(size_t)o * SEQ];
    }
    __syncthreads();

    const int oy = j / HK, ox = j % HK;
    const float* wt = &w1[c * 36];
    float acc = 0.f;
#pragma unroll
    for (int ky = 0; ky < KS; ky++) {
        int iy = oy * DF - PAD + ky;
        if (iy < 0 || iy >= HH) continue;
#pragma unroll
        for (int kx = 0; kx < KS; kx++) {
            int ix = ox * DF - PAD + kx;
            if (ix < 0 || ix >= WW) continue;
            acc += qsm[iy * WW + ix] * wt[ky * KS + kx];
        }
    }
    float x = acc + b1[c];
    float gl = 0.5f * x * (1.0f + erff(x * 0.70710678118654752f));
    g_off1[(size_t)gc * JJ + j] = gl;
}

// ---------------- 1x1 conv + tanh*4 + grid ----------------
__global__ void offgrid_kernel(const float* __restrict__ w2) {
    const int g = blockIdx.x;
    const int j = threadIdx.x;
    float s0 = 0.f, s1 = 0.f;
    for (int c = 0; c < OFFD; c++) {
        float v = g_off1[(size_t)(g * OFFD + c) * JJ + j];
        s0 += w2[c] * v;
        s1 += w2[OFFD + c] * v;
    }
    float offx = tanhf(s0) * OFF_SCALE;
    float offy = tanhf(s1) * OFF_SCALE;
    int x = j % HK, y = j / HK;
    float vx = (float)x + offx;
    float vy = (float)y + offy;
    float sx = 2.0f * vx / (float)(HK - 1) - 1.0f;
    float sy = 2.0f * vy / (float)(HK - 1) - 1.0f;
    g_vgs[(g * JJ + j) * 2 + 0] = sx;
    g_vgs[(g * JJ + j) * 2 + 1] = sy;
}

// ---------------- bilinear grid sample ----------------
__global__ void gsample_kernel(const float* __restrict__ x2) {
    const int blk = blockIdx.x;
    const int g = blk / JJ;
    const int j = blk % JJ;
    const int c = threadIdx.x;
    float sx = g_vgs[(g * JJ + j) * 2 + 0];
    float sy = g_vgs[(g * JJ + j) * 2 + 1];
    float x = (sx + 1.0f) * (WW * 0.5f) - 0.5f;
    float y = (sy + 1.0f) * (HH * 0.5f) - 0.5f;
    float x0f = floorf(x), y0f = floorf(y);
    int x0 = (int)x0f, y0 = (int)y0f;
    float wx1 = x - x0f, wy1 = y - y0f;
    float wx0 = 1.0f - wx1, wy0 = 1.0f - wy1;
    const float* img = &x2[(size_t)(g * (DIM / G) + c) * SEQ + 1];
    float acc = 0.f;
#pragma unroll
    for (int dy = 0; dy < 2; dy++) {
#pragma unroll
        for (int dx = 0; dx < 2; dx++) {
            int ix = x0 + dx, iy = y0 + dy;
            float w = (dx ? wx1 : wx0) * (dy ? wy1 : wy0);
            if (ix >= 0 && ix < WW && iy >= 0 && iy < HH)
                acc += img[iy * WW + ix] * w;
        }
    }
    g_kv[(size_t)(g * (DIM / G) + c) * JJ + j] = acc;
}

// ---------------- FUSED: CPB bias MLP + sim + softmax + out ----------------
// block = (i-tile of 32, group g); bias for both heads 2g, 2g+1 computed into
// smem ps, never touches global memory.
__global__ __launch_bounds__(256)
void fused_attn(const float* __restrict__ W1, const float* __restrict__ B1,
                const float* __restrict__ W2, const float* __restrict__ B2,
                const float* __restrict__ W3, const float* __restrict__ B3) {
    extern __shared__ __align__(16) char smraw[];
    float*    ps   = reinterpret_cast<float*>(smraw);                   // [2][32][148]
    uint32_t* H1s  = reinterpret_cast<uint32_t*>(smraw + PS_B);         // [128][40]
    float*    qs   = reinterpret_cast<float*>(smraw + PS_B + H1_B);    // [32][65]
    uint32_t* W2s  = reinterpret_cast<uint32_t*>(smraw + PS_B + H1_B + QS_B); // [32][72]
    float*    vgss = reinterpret_cast<float*>(smraw + PS_B + H1_B + QS_B + W2S_B);
    uint32_t* Wx2s = reinterpret_cast<uint32_t*>(smraw + PS_B + H1_B + QS_B + W2S_B + VGS_B);
    uint32_t* Wy2s = Wx2s + 32;
    uint32_t* Bb2s = Wy2s + 32;
    float*    B2s  = reinterpret_cast<float*>(Bb2s + 32);               // [64]
    float*    W3s  = B2s + 64;                                          // [128]
    float*    rsum = W3s + 128;                                         // [32]

    const int g = blockIdx.y;
    const int i0 = blockIdx.x * 32;
    const int t = threadIdx.x;

    // --- stage weights + grid ---
    for (int idx = t; idx < 32 * 64; idx += 256) {
        int kk = idx >> 6, n = idx & 63;
        W2s[kk * 72 + n] = pack_bf16x2(W2[(2 * kk) * 64 + n], W2[(2 * kk + 1) * 64 + n]);
    }
    if (t < 32) {
        Wx2s[t] = pack_bf16x2(W1[2 * t], W1[2 * t + 1]);
        Wy2s[t] = pack_bf16x2(W1[64 + 2 * t], W1[64 + 2 * t + 1]);
        Bb2s[t] = pack_bf16x2(B1[2 * t], B1[2 * t + 1]);
    }
    if (t >= 32 && t < 96) B2s[t - 32] = B2[t - 32];
    if (t >= 96 && t < 224) W3s[t - 96] = W3[t - 96];
    for (int idx = t; idx < JJ * 2; idx += 256) vgss[idx] = g_vgs[g * JJ * 2 + idx];
    __syncthreads();

    const int w = t >> 5, lane = t & 31;
    const int gid = lane >> 2, tig = lane & 3;
    const int r0 = w * 16 + gid;     // 8 warps x 16 rows
    const float b30 = B3[0], b31 = B3[1];

    // W2 B-fragments in registers
    uint32_t bw0[4][8], bw1[4][8];
#pragma unroll
    for (int ks = 0; ks < 4; ks++)
#pragma unroll
        for (int nt = 0; nt < 8; nt++) {
            bw0[ks][nt] = W2s[(ks * 8 + tig) * 72 + nt * 8 + gid];
            bw1[ks][nt] = W2s[(ks * 8 + tig + 4) * 72 + nt * 8 + gid];
        }

    const uint4* wx4 = reinterpret_cast<const uint4*>(Wx2s);
    const uint4* wy4 = reinterpret_cast<const uint4*>(Wy2s);
    const uint4* bb4 = reinterpret_cast<const uint4*>(Bb2s);

    // ============ phase 1: MLP bias -> ps (both heads) ============
    for (int ch = 0; ch < 36; ch++) {
        if (t < 128) {
            const int p = ch * 128 + t;           // 0..4607
            const int r = p / JJ;
            const int j = p - r * JJ;
            const int i = i0 + r;
            const int ixx = i % WW, iyy = i / WW;
            const float gqx = (float)ixx * (2.0f / (WW - 1)) - 1.0f;
            const float gqy = (float)iyy * (2.0f / (HH - 1)) - 1.0f;
            const float px = gqx - vgss[j * 2 + 0];
            const float py = gqy - vgss[j * 2 + 1];
            const float fx = copysignf(log1pf(fabsf(px)), px);
            const float fy = copysignf(log1pf(fabsf(py)), py);
            __nv_bfloat162 fx2 = __floats2bfloat162_rn(fx, fx);
            __nv_bfloat162 fy2 = __floats2bfloat162_rn(fy, fy);
            uint4* h1row = reinterpret_cast<uint4*>(&H1s[t * 40]);
#pragma unroll
            for (int q = 0; q < 8; q++) {
                uint4 wx = wx4[q], wy = wy4[q], bb = bb4[q];
                uint4 hv;
                hv.x = h1_bf16x2(fx2, fy2, wx.x, wy.x, bb.x);
                hv.y = h1_bf16x2(fx2, fy2, wx.y, wy.y, bb.y);
                hv.z = h1_bf16x2(fx2, fy2, wx.z, wy.z, bb.z);
                hv.w = h1_bf16x2(fx2, fy2, wx.w, wy.w, bb.w);
                h1row[q] = hv;
            }
        }
        __syncthreads();

        float acc[8][4];
#pragma unroll
        for (int nt = 0; nt < 8; nt++)
#pragma unroll
            for (int c = 0; c < 4; c++) acc[nt][c] = 0.f;

#pragma unroll
        for (int ks = 0; ks < 4; ks++) {
            const int kk0 = ks * 8;
            uint32_t a[4];
            a[0] = H1s[r0 * 40 + kk0 + tig];
            a[1] = H1s[(r0 + 8) * 40 + kk0 + tig];
            a[2] = H1s[r0 * 40 + kk0 + tig + 4];
            a[3] = H1s[(r0 + 8) * 40 + kk0 + tig + 4];
#pragma unroll
            for (int nt = 0; nt < 8; nt++)
                mma_bf16(acc[nt], a, bw0[ks][nt], bw1[ks][nt]);
        }

        // epilogue: +B2, relu, xW3, quad-reduce, write to ps (both heads)
        float sa0 = 0.f, sa1 = 0.f, sb0 = 0.f, sb1 = 0.f;
#pragma unroll
        for (int nt = 0; nt < 8; nt++) {
            int n0 = nt * 8 + 2 * tig;
            int n1 = n0 + 1;
            float h;
            h = fmaxf(acc[nt][0] + B2s[n0], 0.f);
            sa0 += h * W3s[2 * n0]; sa1 += h * W3s[2 * n0 + 1];
            h = fmaxf(acc[nt][1] + B2s[n1], 0.f);
            sa0 += h * W3s[2 * n1]; sa1 += h * W3s[2 * n1 + 1];
            h = fmaxf(acc[nt][2] + B2s[n0], 0.f);
            sb0 += h * W3s[2 * n0]; sb1 += h * W3s[2 * n0 + 1];
            h = fmaxf(acc[nt][3] + B2s[n1], 0.f);
            sb0 += h * W3s[2 * n1]; sb1 += h * W3s[2 * n1 + 1];
        }
#pragma unroll
        for (int off = 1; off <= 2; off <<= 1) {
            sa0 += __shfl_xor_sync(0xffffffffu, sa0, off);
            sa1 += __shfl_xor_sync(0xffffffffu, sa1, off);
            sb0 += __shfl_xor_sync(0xffffffffu, sb0, off);
            sb1 += __shfl_xor_sync(0xffffffffu, sb1, off);
        }
        if (tig == 0) {
#pragma unroll
            for (int half = 0; half < 2; half++) {
                int row = r0 + half * 8;          // w*16 + gid + half*8
                int p = ch * 128 + row;
                int r = p / JJ;
                int j = p - r * JJ;
                float o0 = (half ? sb0 : sa0) + b30;
                float o1 = (half ? sb1 : sa1) + b31;
                ps[r * 148 + j] = o0;
                ps[PS_F / 2 + r * 148 + j] = o1;
            }
        }
        __syncthreads();
    }

    // ============ phase 2: attention per head ============
    float4* ps4all = reinterpret_cast<float4*>(ps);
    for (int h2 = 0; h2 < 2; h2++) {
        const int h = g * 2 + h2;
        float4* ps4 = ps4all + h2 * (PS_F / 2 / 4);   // [32][37] float4

        // q tile (coalesced over i)
        for (int idx = t; idx < 32 * 64; idx += 256) {
            int r = idx & 31, d = idx >> 5;
            int i = i0 + r;
            qs[r * 65 + d] = (i < NPOS) ? g_q[(size_t)(h * 64 + d) * NPOS + i] * SCALE : 0.f;
        }
        __syncthreads();

        // sim accumulated onto bias already in ps
        const float4* k4 = reinterpret_cast<const float4*>(g_k + (size_t)h * 64 * JJ);
        for (int idx = t; idx < 8 * 36; idx += 256) {
            int rg = idx / 36, j4 = idx - rg * 36;
            float4 s0 = {0, 0, 0, 0}, s1 = {0, 0, 0, 0}, s2 = {0, 0, 0, 0}, s3 = {0, 0, 0, 0};
#pragma unroll 16
            for (int d = 0; d < 64; d++) {
                float4 kv = k4[d * 36 + j4];
                float q0 = qs[(rg * 4 + 0) * 65 + d], q1 = qs[(rg * 4 + 1) * 65 + d];
                float q2 = qs[(rg * 4 + 2) * 65 + d], q3 = qs[(rg * 4 + 3) * 65 + d];
                s0.x = fmaf(q0, kv.x, s0.x); s0.y = fmaf(q0, kv.y, s0.y);
                s0.z = fmaf(q0, kv.z, s0.z); s0.w = fmaf(q0, kv.w, s0.w);
                s1.x = fmaf(q1, kv.x, s1.x); s1.y = fmaf(q1, kv.y, s1.y);
                s1.z = fmaf(q1, kv.z, s1.z); s1.w = fmaf(q1, kv.w, s1.w);
                s2.x = fmaf(q2, kv.x, s2.x); s2.y = fmaf(q2, kv.y, s2.y);
                s2.z = fmaf(q2, kv.z, s2.z); s2.w = fmaf(q2, kv.w, s2.w);
                s3.x = fmaf(q3, kv.x, s3.x); s3.y = fmaf(q3, kv.y, s3.y);
                s3.z = fmaf(q3, kv.z, s3.z); s3.w = fmaf(q3, kv.w, s3.w);
            }
            float4 sv[4] = {s0, s1, s2, s3};
#pragma unroll
            for (int u = 0; u < 4; u++) {
                int r = rg * 4 + u;
                float4 b = ps4[r * 37 + j4];
                b.x += sv[u].x; b.y += sv[u].y; b.z += sv[u].z; b.w += sv[u].w;
                ps4[r * 37 + j4] = b;
            }
        }
        __syncthreads();

        // softmax: warp w owns rows {w, w+8, w+16, w+24}
        float* psl = reinterpret_cast<float*>(ps4);
#pragma unroll
        for (int rr = 0; rr < 4; rr++) {
            int row = w + rr * 8;
            float* pr = psl + row * 148;
            float m = -1e30f;
            for (int j = lane; j < JJ; j += 32) m = fmaxf(m, pr[j]);
#pragma unroll
            for (int o = 16; o; o >>= 1) m = fmaxf(m, __shfl_xor_sync(0xffffffffu, m, o));
            float s = 0.f;
            for (int j = lane; j < JJ; j += 32) {
                float e = fast_exp(pr[j] - m);
                pr[j] = e;
                s += e;
            }
#pragma unroll
            for (int o = 16; o; o >>= 1) s += __shfl_xor_sync(0xffffffffu, s, o);
            if (lane == 0) rsum[row] = s;
        }
        __syncthreads();

        // out
        const float4* v4 = reinterpret_cast<const float4*>(g_v + (size_t)h * 64 * JJ);
        for (int idx = t; idx < 16 * 32; idx += 256) {
            int dg = idx >> 5, r = idx & 31;
            int i = i0 + r;
            if (i >= NPOS) continue;
            float o0 = 0.f, o1 = 0.f, o2 = 0.f, o3 = 0.f;
#pragma unroll 4
            for (int j4 = 0; j4 < 36; j4++) {
                float4 pv = ps4[r * 37 + j4];
                float4 v0 = v4[(dg * 4 + 0) * 36 + j4];
                float4 v1 = v4[(dg * 4 + 1) * 36 + j4];
                float4 v2 = v4[(dg * 4 + 2) * 36 + j4];
                float4 v3 = v4[(dg * 4 + 3) * 36 + j4];
                o0 += pv.x * v0.x + pv.y * v0.y + pv.z * v0.z + pv.w * v0.w;
                o1 += pv.x * v1.x + pv.y * v1.y + pv.z * v1.z + pv.w * v1.w;
                o2 += pv.x * v2.x + pv.y * v2.y + pv.z * v2.z + pv.w * v2.w;
                o3 += pv.x * v3.x + pv.y * v3.y + pv.z * v3.z + pv.w * v3.w;
            }
            float inv = 1.0f / rsum[r];
            g_ao[(size_t)(h * 64 + dg * 4 + 0) * NPOS + i] = o0 * inv;
            g_ao[(size_t)(h * 64 + dg * 4 + 1) * NPOS + i] = o1 * inv;
            g_ao[(size_t)(h * 64 + dg * 4 + 2) * NPOS + i] = o2 * inv;
            g_ao[(size_t)(h * 64 + dg * 4 + 3) * NPOS + i] = o3 * inv;
        }
        __syncthreads();
    }
}

// ---------------- launcher ----------------
extern "C" void kernel_launch(void* const* d_in, const int* in_sizes, int n_in,
                              void* d_out, int out_size) {
    const float* x1    = (const float*)d_in[0];
    const float* x2    = (const float*)d_in[1];
    const float* w_off1= (const float*)d_in[2];
    const float* b_off1= (const float*)d_in[3];
    const float* w_off2= (const float*)d_in[4];
    const float* wq    = (const float*)d_in[5];
    const float* wk    = (const float*)d_in[6];
    const float* wv    = (const float*)d_in[7];
    const float* wout  = (const float*)d_in[8];
    const float* bout  = (const float*)d_in[9];
    const float* cpb_w1= (const float*)d_in[10];
    const float* cpb_b1= (const float*)d_in[11];
    const float* cpb_w2= (const float*)d_in[12];
    const float* cpb_b2= (const float*)d_in[13];
    const float* cpb_w3= (const float*)d_in[14];
    const float* cpb_b3= (const float*)d_in[15];
    float* out = (float*)d_out;

    float *qp, *kvp, *kp, *vp, *aop;
    cudaGetSymbolAddress((void**)&qp,  g_q);
    cudaGetSymbolAddress((void**)&kvp, g_kv);
    cudaGetSymbolAddress((void**)&kp,  g_k);
    cudaGetSymbolAddress((void**)&vp,  g_v);
    cudaGetSymbolAddress((void**)&aop, g_ao);

    cudaFuncSetAttribute(fused_attn, cudaFuncAttributeMaxDynamicSharedMemorySize,
                         FA_SMEM);

    // 1) q = wq @ f1
    tf32gemm<<<dim3(40, 8, 1), 256>>>(wq, x1, qp, INNER, NPOS, DIM, SEQ, 1, NPOS, 0,
                                      nullptr, nullptr, nullptr);

    // 2) depthwise conv + gelu (+ cls copy)
    dconv_kernel<<<INNER, JJ>>>(w_off1, b_off1, x1, out);

    // 3) 1x1 conv + tanh + grid
    offgrid_kernel<<<G, JJ>>>(w_off2);

    // 4) bilinear sample
    gsample_kernel<<<G * JJ, 64>>>(x2);

    // 5) k, v GEMMs (one launch)
    tf32gemm<<<dim3(3, 8, 2), 256>>>(wk, kvp, kp, INNER, JJ, DIM, JJ, 0, JJ, 0,
                                     nullptr, wv, vp);

    // 6) fused CPB-bias + attention
    fused_attn<<<dim3((NPOS + 31) / 32, G), 256, FA_SMEM>>>(
        cpb_w1, cpb_b1, cpb_w2, cpb_b2, cpb_w3, cpb_b3);

    // 7) wout @ attn_out + bout
    tf32gemm<<<dim3(40, 4, 1), 256>>>(wout, aop, out, DIM, NPOS, INNER, NPOS, 0, SEQ, 1,
                                      bout, nullptr, nullptr);
}